// round 2
// baseline (speedup 1.0000x reference)
#include <cuda_runtime.h>
#include <math.h>

#define BB 64
#define SS 4096
#define EE 50
#define TT 20

#define CS 128
#define HALO 5
#define RR (CS + 2*HALO)          // 138
#define NSTRIP 16
#define NP 9                      // 16*9 = 144 >= 138
#define XSTR2 146                 // row length in float2 units (positions -1..144 stored at idx 0..145)
#define NTHREADS 400

// smem carve (in float2 units where noted)
#define WS2_N (150*25)            // paired conv weights
#define XS2_N (EE*XSTR2)          // duplicated activations
#define SMEM_BYTES ((WS2_N + 25 + XS2_N) * 8 + (1000 + 20) * 4)

typedef unsigned long long ull;

__device__ float g_em[(size_t)SS * BB * TT];           // raw emissions [s][b][t]
__device__ float g_ee[(size_t)(SS + 32) * BB * TT];    // exp(emissions), padded for prefetch
__device__ float g_den[BB];                            // den - num per batch

__device__ __forceinline__ void fma2(ull& d, ull a, ull b) {
    asm("fma.rn.f32x2 %0, %1, %2, %0;" : "+l"(d) : "l"(a), "l"(b));
}
__device__ __forceinline__ float2 u2f2(ull u) {
    float2 f;
    asm("mov.b64 {%0, %1}, %2;" : "=f"(f.x), "=f"(f.y) : "l"(u));
    return f;
}

// ---------------------------------------------------------------------------
// Fused: embed gather -> 5x (conv1d + swish residual) -> emissions (+exp)
// grid (S/CS, B), 400 threads = (25 o-pairs) x (16 strips), dyn smem ~92.7KB
// x stored DUPLICATED (x,x) per float2 so packed operands need no MOVs.
// ---------------------------------------------------------------------------
__global__ __launch_bounds__(NTHREADS, 2)
void conv_emit_kernel(const int* __restrict__ token_id,
                      const float* __restrict__ embed_table,
                      const float* __restrict__ conv_w,
                      const float* __restrict__ conv_b,
                      const float* __restrict__ out_w,
                      const float* __restrict__ out_b)
{
    extern __shared__ float2 smf2[];
    float2* ws2 = smf2;                 // [ (i*3+k) ][ op ] : (w[2op], w[2op+1])
    float2* cb2 = ws2 + WS2_N;          // 25
    float2* xs2 = cb2 + 25;             // [e][idx] duplicated values
    float*  ow  = (float*)(xs2 + XS2_N);// [t][e] 1000
    float*  ob  = ow + 1000;            // 20

    const int tid = threadIdx.x;
    const int b   = blockIdx.y;
    const int s0  = blockIdx.x * CS;

    // paired conv weights: ws2[row][op] = (conv_w[2op][row], conv_w[2op+1][row]), row = i*3+k
    for (int idx = tid; idx < WS2_N; idx += NTHREADS) {
        int row = idx / 25; int op = idx - row * 25;
        float2 w;
        w.x = conv_w[(2*op    ) * 150 + row];
        w.y = conv_w[(2*op + 1) * 150 + row];
        ws2[idx] = w;
    }
    for (int idx = tid; idx < 1000; idx += NTHREADS) ow[idx] = out_w[idx];
    if (tid < 25) { float2 c; c.x = conv_b[2*tid]; c.y = conv_b[2*tid+1]; cb2[tid] = c; }
    if (tid < 20) ob[tid] = out_b[tid];

    // zero whole xs2 then gather embeddings (duplicated)
    for (int idx = tid; idx < XS2_N; idx += NTHREADS) xs2[idx] = make_float2(0.f, 0.f);
    __syncthreads();
    for (int idx = tid; idx < EE * RR; idx += NTHREADS) {
        int p = idx / EE; int e = idx - p * EE;
        int s = s0 - HALO + p;
        if (s >= 0 && s < SS) {
            int tok = token_id[b * SS + s];
            float v = embed_table[tok * EE + e];
            xs2[e * XSTR2 + p + 1] = make_float2(v, v);
        }
    }
    __syncthreads();

    const int op    = tid % 25;
    const int strip = tid / 25;            // 0..15
    const int pb    = strip * NP;
    const float2 cb = cb2[op];
    const int pad_lo = (s0 == 0) ? HALO : 0;
    int pad_hi = SS - s0 + HALO; if (pad_hi > RR) pad_hi = RR;

    const ull* xsu = (const ull*)xs2;
    const ull* wsu = (const ull*)ws2;

    for (int iter = 1; iter <= 5; ++iter) {
        ull acc[NP];
        #pragma unroll
        for (int j = 0; j < NP; ++j) acc[j] = 0ull;

        #pragma unroll 1
        for (int i = 0; i < EE; ++i) {
            ull w0 = wsu[(i * 3 + 0) * 25 + op];
            ull w1 = wsu[(i * 3 + 1) * 25 + op];
            ull w2 = wsu[(i * 3 + 2) * 25 + op];
            const ull* xr = xsu + i * XSTR2 + pb;   // xr[0] = pos pb-1
            ull xm = xr[0];
            ull xc = xr[1];
            #pragma unroll
            for (int j = 0; j < NP; ++j) {
                ull xp = xr[j + 2];
                fma2(acc[j], w0, xm);
                fma2(acc[j], w1, xc);
                fma2(acc[j], w2, xp);
                xm = xc; xc = xp;
            }
        }
        __syncthreads();

        int lo = (iter > pad_lo) ? iter : pad_lo;
        int hi = RR - iter; if (hi > pad_hi) hi = pad_hi;
        const int o0 = 2 * op, o1 = 2 * op + 1;
        #pragma unroll
        for (int j = 0; j < NP; ++j) {
            int p = pb + j;
            if (p >= lo && p < hi) {
                float2 a = u2f2(acc[j]);
                float y0 = a.x + cb.x;
                float y1 = a.y + cb.y;
                float sw0 = y0 * (1.0f / (1.0f + __expf(-y0)));
                float sw1 = y1 * (1.0f / (1.0f + __expf(-y1)));
                int i0 = o0 * XSTR2 + p + 1;
                int i1 = o1 * XSTR2 + p + 1;
                float nx0 = xs2[i0].x + sw0;
                float nx1 = xs2[i1].x + sw1;
                xs2[i0] = make_float2(nx0, nx0);
                xs2[i1] = make_float2(nx1, nx1);
            }
        }
        __syncthreads();
    }

    // emissions for q in [0, CS)
    for (int idx = tid; idx < TT * CS; idx += NTHREADS) {
        int t = idx % TT;
        int q = idx / TT;
        int p = q + HALO;
        int s = s0 + q;
        float acc = ob[t];
        const float* owt = &ow[t * EE];
        #pragma unroll 5
        for (int e = 0; e < EE; ++e)
            acc = fmaf(xs2[e * XSTR2 + p + 1].x, owt[e], acc);
        int gi = (s * BB + b) * TT + t;
        g_em[gi] = acc;
        g_ee[gi] = __expf(acc);
    }
}

// ---------------------------------------------------------------------------
// CRF forward + numerator fused. grid(B), 288 threads:
//   warp 0       : scaled probability-space forward scan (latency-bound)
//   warps 1..8   : gold-path numerator sum (throughput, hidden under scan)
// ---------------------------------------------------------------------------
__device__ __forceinline__ float crf_step(float beta, const float* Et, float e)
{
    float a0 = 0.f, a1 = 0.f, a2 = 0.f, a3 = 0.f;
    #pragma unroll
    for (int i = 0; i < TT; i += 4) {
        a0 = fmaf(__shfl_sync(0xffffffffu, beta, i + 0), Et[i + 0], a0);
        a1 = fmaf(__shfl_sync(0xffffffffu, beta, i + 1), Et[i + 1], a1);
        a2 = fmaf(__shfl_sync(0xffffffffu, beta, i + 2), Et[i + 2], a2);
        a3 = fmaf(__shfl_sync(0xffffffffu, beta, i + 3), Et[i + 3], a3);
    }
    return e * ((a0 + a1) + (a2 + a3));
}

__global__ __launch_bounds__(288, 4)
void crf_num_kernel(const int* __restrict__ tag,
                    const float* __restrict__ start_trans,
                    const float* __restrict__ end_trans,
                    const float* __restrict__ trans)
{
    __shared__ float red[256];
    __shared__ float den_sh;
    const int b   = blockIdx.x;
    const int tid = threadIdx.x;

    if (tid >= 32) {
        // ---- numerator ----
        float sum = 0.0f;
        for (int s = tid - 32; s < SS; s += 256) {
            int tg = tag[b * SS + s];
            sum += g_em[(s * BB + b) * TT + tg];
            if (s > 0)      sum += trans[tag[b * SS + s - 1] * TT + tg];
            if (s == 0)     sum += start_trans[tg];
            if (s == SS-1)  sum += end_trans[tg];
        }
        red[tid - 32] = sum;
    } else {
        // ---- forward scan, scaled prob space ----
        const int j = tid;
        const bool ok = (j < TT);
        const int jj = ok ? j : 0;

        float Et[TT];
        #pragma unroll
        for (int i = 0; i < TT; ++i) Et[i] = ok ? __expf(trans[i * TT + jj]) : 0.0f;

        float beta = ok ? __expf(start_trans[jj]) * g_ee[b * TT + jj] : 0.0f;
        float L = 0.0f;

        float ea[8], eb[8];
        #pragma unroll
        for (int k = 0; k < 8; ++k) ea[k] = g_ee[((1 + k) * BB + b) * TT + jj];

        const int NG = (SS - 1 + 7) / 8;   // 512 (even)
        for (int g = 0; g < NG; g += 2) {
            int bn = 1 + (g + 1) * 8;
            #pragma unroll
            for (int k = 0; k < 8; ++k) eb[k] = g_ee[((bn + k) * BB + b) * TT + jj];
            int bs = 1 + g * 8;
            #pragma unroll
            for (int k = 0; k < 8; ++k)
                if (bs + k < SS) beta = crf_step(beta, Et, ea[k]);
            {
                float m = beta;
                #pragma unroll
                for (int off = 16; off > 0; off >>= 1)
                    m = fmaxf(m, __shfl_xor_sync(0xffffffffu, m, off));
                L += __log2f(m);
                beta *= __frcp_rn(m);
            }
            int bn2 = 1 + (g + 2) * 8;
            #pragma unroll
            for (int k = 0; k < 8; ++k) ea[k] = g_ee[((bn2 + k) * BB + b) * TT + jj];
            #pragma unroll
            for (int k = 0; k < 8; ++k)
                if (bn + k < SS) beta = crf_step(beta, Et, eb[k]);
            {
                float m = beta;
                #pragma unroll
                for (int off = 16; off > 0; off >>= 1)
                    m = fmaxf(m, __shfl_xor_sync(0xffffffffu, m, off));
                L += __log2f(m);
                beta *= __frcp_rn(m);
            }
        }

        float v = ok ? beta * __expf(end_trans[jj]) : 0.0f;
        #pragma unroll
        for (int off = 16; off > 0; off >>= 1) v += __shfl_xor_sync(0xffffffffu, v, off);
        if (j == 0) den_sh = (L + __log2f(v)) * 0.69314718055994531f;
    }
    __syncthreads();

    // reduce numerator partials (256 entries) with first 128 threads
    for (int k = 128; k > 0; k >>= 1) {
        if (tid < k) red[tid] += red[tid + k];
        __syncthreads();
    }
    if (tid == 0) g_den[b] = den_sh - red[0];
}

// ---------------------------------------------------------------------------
// Final: out = sum_b (den_b - num_b) = -llh
// ---------------------------------------------------------------------------
__global__ void final_kernel(float* __restrict__ out)
{
    __shared__ float red[64];
    int t = threadIdx.x;
    red[t] = g_den[t];
    __syncthreads();
    for (int k = 32; k > 0; k >>= 1) {
        if (t < k) red[t] += red[t + k];
        __syncthreads();
    }
    if (t == 0) out[0] = red[0];
}

extern "C" void kernel_launch(void* const* d_in, const int* in_sizes, int n_in,
                              void* d_out, int out_size)
{
    const int*   token_id    = (const int*)d_in[0];
    const int*   tag_id      = (const int*)d_in[1];
    const float* embed_table = (const float*)d_in[2];
    const float* conv_w      = (const float*)d_in[3];
    const float* conv_b      = (const float*)d_in[4];
    const float* out_w       = (const float*)d_in[5];
    const float* out_b       = (const float*)d_in[6];
    const float* start_trans = (const float*)d_in[7];
    const float* end_trans   = (const float*)d_in[8];
    const float* trans       = (const float*)d_in[9];

    cudaFuncSetAttribute(conv_emit_kernel,
                         cudaFuncAttributeMaxDynamicSharedMemorySize, SMEM_BYTES);

    dim3 grid(SS / CS, BB);
    conv_emit_kernel<<<grid, NTHREADS, SMEM_BYTES>>>(token_id, embed_table, conv_w,
                                                     conv_b, out_w, out_b);
    crf_num_kernel<<<BB, 288>>>(tag_id, start_trans, end_trans, trans);
    final_kernel<<<1, 64>>>((float*)d_out);
}

// round 4
// speedup vs baseline: 2.2467x; 2.2467x over previous
#include <cuda_runtime.h>
#include <cuda_fp16.h>
#include <math.h>

#define BB 64
#define SS 4096
#define EE 50
#define TT 20

#define CS 128
#define HALO 5
#define RR (CS + 2*HALO)          // 138 positions (p = 0..137), outputs valid per layer shrink
#define NSTRIP 16
#define NP 9                      // 16*9 = 144 >= 138
#define XSTR2 146                 // half2 row stride (pos -1..144 at idx 0..145)
#define NTHREADS 400

#define WS2_N (150*25)            // paired conv weights (half2)
#define XS2_N (EE*XSTR2)          // duplicated activations (half2)
// bytes: ws2 + xs2 (half2=4B) + cb2 (float2) + ow (f32) + ob (f32)
#define SMEM_BYTES ((WS2_N + XS2_N) * 4 + 25 * 8 + (1000 + 20) * 4)

__device__ float g_em[(size_t)SS * BB * TT];           // raw emissions [s][b][t]
__device__ float g_ee[(size_t)(SS + 40) * BB * TT];    // exp(emissions), padded for prefetch
__device__ float g_num[BB];
__device__ float g_fvec[BB][TT];
__device__ float g_bvec[BB][TT];
__device__ float g_fL[BB];
__device__ float g_bL[BB];

// ---------------------------------------------------------------------------
// Fused: embed gather -> 5x (conv1d + swish residual) -> emissions (+exp)
// grid (S/CS=32, B=64), 400 threads = (25 o-pairs) x (16 strips), smem ~49KB
// x stored DUPLICATED (h,h) per half2; weights paired (w[2o],w[2o+1]).
// All MMA work is HFMA2 (2 MAC/instr, full rate) with LDS.32 operands.
// ---------------------------------------------------------------------------
__global__ __launch_bounds__(NTHREADS, 3)
void conv_emit_kernel(const int* __restrict__ token_id,
                      const float* __restrict__ embed_table,
                      const float* __restrict__ conv_w,
                      const float* __restrict__ conv_b,
                      const float* __restrict__ out_w,
                      const float* __restrict__ out_b)
{
    extern __shared__ __half2 smh2[];
    __half2* ws2 = smh2;                  // [(i*3+k)][op]
    __half2* xs2 = ws2 + WS2_N;           // [e][idx]
    float2*  cb2 = (float2*)(xs2 + XS2_N);// 25
    float*   ow  = (float*)(cb2 + 25);    // [t][e] 1000
    float*   ob  = ow + 1000;             // 20

    const int tid = threadIdx.x;
    const int b   = blockIdx.y;
    const int s0  = blockIdx.x * CS;

    // paired conv weights: ws2[row*25+op] = (w[2op][row], w[2op+1][row]), row = i*3+k
    for (int idx = tid; idx < WS2_N; idx += NTHREADS) {
        int row = idx / 25; int op = idx - row * 25;
        float a = conv_w[(2*op    ) * 150 + row];
        float c = conv_w[(2*op + 1) * 150 + row];
        ws2[idx] = __floats2half2_rn(a, c);
    }
    for (int idx = tid; idx < 1000; idx += NTHREADS) ow[idx] = out_w[idx];
    if (tid < 25) cb2[tid] = make_float2(conv_b[2*tid], conv_b[2*tid+1]);
    if (tid < 20) ob[tid] = out_b[tid];

    // zero xs2, then gather embeddings duplicated
    for (int idx = tid; idx < XS2_N; idx += NTHREADS) xs2[idx] = __floats2half2_rn(0.f, 0.f);
    __syncthreads();
    for (int idx = tid; idx < EE * RR; idx += NTHREADS) {
        int p = idx / EE; int e = idx - p * EE;
        int s = s0 - HALO + p;
        if (s >= 0 && s < SS) {
            int tok = token_id[b * SS + s];
            float v = embed_table[tok * EE + e];
            xs2[e * XSTR2 + p + 1] = __floats2half2_rn(v, v);
        }
    }
    __syncthreads();

    const int op    = tid % 25;
    const int strip = tid / 25;            // 0..15
    const int pb    = strip * NP;
    const float2 cb = cb2[op];
    const int pad_lo = (s0 == 0) ? HALO : 0;
    int pad_hi = SS - s0 + HALO; if (pad_hi > RR) pad_hi = RR;

    for (int iter = 1; iter <= 5; ++iter) {
        __half2 acc[NP];
        #pragma unroll
        for (int j = 0; j < NP; ++j) acc[j] = __floats2half2_rn(0.f, 0.f);

        #pragma unroll 1
        for (int i = 0; i < EE; ++i) {
            __half2 w0 = ws2[(i * 3 + 0) * 25 + op];
            __half2 w1 = ws2[(i * 3 + 1) * 25 + op];
            __half2 w2 = ws2[(i * 3 + 2) * 25 + op];
            const __half2* xr = xs2 + i * XSTR2 + pb;   // xr[0] = position pb-1
            __half2 xv[NP + 2];
            #pragma unroll
            for (int j = 0; j < NP + 2; ++j) xv[j] = xr[j];
            #pragma unroll
            for (int j = 0; j < NP; ++j) {
                acc[j] = __hfma2(w0, xv[j],     acc[j]);
                acc[j] = __hfma2(w1, xv[j + 1], acc[j]);
                acc[j] = __hfma2(w2, xv[j + 2], acc[j]);
            }
        }
        __syncthreads();

        int lo = (iter > pad_lo) ? iter : pad_lo;
        int hi = RR - iter; if (hi > pad_hi) hi = pad_hi;
        const int o0 = 2 * op, o1 = 2 * op + 1;
        #pragma unroll
        for (int j = 0; j < NP; ++j) {
            int p = pb + j;
            if (p >= lo && p < hi) {
                float y0 = __low2float(acc[j])  + cb.x;
                float y1 = __high2float(acc[j]) + cb.y;
                float sw0 = __fdividef(y0, 1.0f + __expf(-y0));
                float sw1 = __fdividef(y1, 1.0f + __expf(-y1));
                int i0 = o0 * XSTR2 + p + 1;
                int i1 = o1 * XSTR2 + p + 1;
                float nx0 = __low2float(xs2[i0]) + sw0;
                float nx1 = __low2float(xs2[i1]) + sw1;
                xs2[i0] = __floats2half2_rn(nx0, nx0);
                xs2[i1] = __floats2half2_rn(nx1, nx1);
            }
        }
        __syncthreads();
    }

    // emissions for q in [0, CS)
    for (int idx = tid; idx < TT * CS; idx += NTHREADS) {
        int t = idx % TT;
        int q = idx / TT;
        int p = q + HALO;
        int s = s0 + q;
        float acc = ob[t];
        const float* owt = &ow[t * EE];
        #pragma unroll 5
        for (int e = 0; e < EE; ++e)
            acc = fmaf(__low2float(xs2[e * XSTR2 + p + 1]), owt[e], acc);
        int gi = (s * BB + b) * TT + t;
        g_em[gi] = acc;
        g_ee[gi] = __expf(acc);
    }
}

// ===========================================================================
// CRF: grid (BB, 3) x 32 threads.
//   y=0: forward scan t=1..2048   y=1: backward scan t=4094..2048   y=2: numerator
// den = ln2*(Lf+Lb) + log(sum_j alpha_2048[j]*beta_2048[j])
// ===========================================================================
__device__ __forceinline__ float crf_dot(float c, const float* E)
{
    float a0 = 0.f, a1 = 0.f, a2 = 0.f, a3 = 0.f;
    #pragma unroll
    for (int i = 0; i < TT; i += 4) {
        a0 = fmaf(__shfl_sync(0xffffffffu, c, i + 0), E[i + 0], a0);
        a1 = fmaf(__shfl_sync(0xffffffffu, c, i + 1), E[i + 1], a1);
        a2 = fmaf(__shfl_sync(0xffffffffu, c, i + 2), E[i + 2], a2);
        a3 = fmaf(__shfl_sync(0xffffffffu, c, i + 3), E[i + 3], a3);
    }
    return (a0 + a1) + (a2 + a3);
}
__device__ __forceinline__ float warp_max(float v) {
    #pragma unroll
    for (int o = 16; o > 0; o >>= 1) v = fmaxf(v, __shfl_xor_sync(0xffffffffu, v, o));
    return v;
}

__global__ void crf_kernel(const int* __restrict__ tag,
                           const float* __restrict__ start_trans,
                           const float* __restrict__ end_trans,
                           const float* __restrict__ trans)
{
    const int b = blockIdx.x;
    const int dir = blockIdx.y;
    const int j = threadIdx.x;
    const bool ok = (j < TT);
    const int jj = ok ? j : 0;

    if (dir == 2) {
        float sum = 0.0f;
        for (int s = j; s < SS; s += 32) {
            int tg = tag[b * SS + s];
            sum += g_em[(s * BB + b) * TT + tg];
            if (s > 0)      sum += trans[tag[b * SS + s - 1] * TT + tg];
            if (s == 0)     sum += start_trans[tg];
            if (s == SS-1)  sum += end_trans[tg];
        }
        #pragma unroll
        for (int o = 16; o > 0; o >>= 1) sum += __shfl_xor_sync(0xffffffffu, sum, o);
        if (j == 0) g_num[b] = sum;
        return;
    }

    float E[TT];
    float val, L = 0.0f;
    float ea[8], eb[8];

    if (dir == 0) {
        // forward: lane j holds alpha[j]; E[i] = exp(trans[i][j])
        #pragma unroll
        for (int i = 0; i < TT; ++i) E[i] = ok ? __expf(trans[i * TT + jj]) : 0.0f;
        val = ok ? __expf(start_trans[jj]) * g_ee[(0 * BB + b) * TT + jj] : 0.0f;
        #pragma unroll
        for (int k = 0; k < 8; ++k) ea[k] = g_ee[((1 + k) * BB + b) * TT + jj];
        for (int g = 0; g < 256; g += 2) {
            int t1 = 1 + (g + 1) * 8;
            #pragma unroll
            for (int k = 0; k < 8; ++k) eb[k] = g_ee[((t1 + k) * BB + b) * TT + jj];
            #pragma unroll
            for (int k = 0; k < 8; ++k) val = ea[k] * crf_dot(val, E);
            { float m = warp_max(val); L += __log2f(m); val *= __frcp_rn(m); }
            int t2 = 1 + (g + 2) * 8;
            #pragma unroll
            for (int k = 0; k < 8; ++k) ea[k] = g_ee[((t2 + k) * BB + b) * TT + jj];
            #pragma unroll
            for (int k = 0; k < 8; ++k) val = eb[k] * crf_dot(val, E);
            { float m = warp_max(val); L += __log2f(m); val *= __frcp_rn(m); }
        }
        if (ok) g_fvec[b][jj] = val;
        if (j == 0) g_fL[b] = L;
    } else {
        // backward: lane j holds beta[j]; E[i] = exp(trans[j][i])
        // beta_t[j] = sum_i exp(trans[j][i]) * e_{t+1}[i] * beta_{t+1}[i]
        // steps m=0..2046: t = 4094-m, uses e[4095-m]
        #pragma unroll
        for (int i = 0; i < TT; ++i) E[i] = ok ? __expf(trans[jj * TT + i]) : 0.0f;
        val = ok ? __expf(end_trans[jj]) : 0.0f;
        #pragma unroll
        for (int k = 0; k < 8; ++k) ea[k] = g_ee[((size_t)(4095 - k) * BB + b) * TT + jj];
        for (int g = 0; g < 256; g += 2) {
            int m1 = (g + 1) * 8;
            #pragma unroll
            for (int k = 0; k < 8; ++k) {
                int t = 4095 - (m1 + k);
                eb[k] = (t >= 0) ? g_ee[((size_t)t * BB + b) * TT + jj] : 0.0f;
            }
            int m0 = g * 8;
            #pragma unroll
            for (int k = 0; k < 8; ++k)
                if (m0 + k < 2047) val = crf_dot(ea[k] * val, E);
            { float m = warp_max(val); L += __log2f(m); val *= __frcp_rn(m); }
            int m2 = (g + 2) * 8;
            #pragma unroll
            for (int k = 0; k < 8; ++k) {
                int t = 4095 - (m2 + k);
                ea[k] = (t >= 0) ? g_ee[((size_t)t * BB + b) * TT + jj] : 0.0f;
            }
            #pragma unroll
            for (int k = 0; k < 8; ++k)
                if (m1 + k < 2047) val = crf_dot(eb[k] * val, E);
            { float m = warp_max(val); L += __log2f(m); val *= __frcp_rn(m); }
        }
        if (ok) g_bvec[b][jj] = val;
        if (j == 0) g_bL[b] = L;
    }
}

// ===========================================================================
// Combine: out = sum_b (den_b - num_b)
// ===========================================================================
__global__ void final_kernel(float* __restrict__ out)
{
    __shared__ float red[64];
    int t = threadIdx.x;
    float s = 0.0f;
    #pragma unroll
    for (int i = 0; i < TT; ++i) s += g_fvec[t][i] * g_bvec[t][i];
    float den = (g_fL[t] + g_bL[t]) * 0.69314718055994531f + logf(s);
    red[t] = den - g_num[t];
    __syncthreads();
    for (int k = 32; k > 0; k >>= 1) {
        if (t < k) red[t] += red[t + k];
        __syncthreads();
    }
    if (t == 0) out[0] = red[0];
}

extern "C" void kernel_launch(void* const* d_in, const int* in_sizes, int n_in,
                              void* d_out, int out_size)
{
    const int*   token_id    = (const int*)d_in[0];
    const int*   tag_id      = (const int*)d_in[1];
    const float* embed_table = (const float*)d_in[2];
    const float* conv_w      = (const float*)d_in[3];
    const float* conv_b      = (const float*)d_in[4];
    const float* out_w       = (const float*)d_in[5];
    const float* out_b       = (const float*)d_in[6];
    const float* start_trans = (const float*)d_in[7];
    const float* end_trans   = (const float*)d_in[8];
    const float* trans       = (const float*)d_in[9];

    cudaFuncSetAttribute(conv_emit_kernel,
                         cudaFuncAttributeMaxDynamicSharedMemorySize, SMEM_BYTES);

    dim3 grid(SS / CS, BB);
    conv_emit_kernel<<<grid, NTHREADS, SMEM_BYTES>>>(token_id, embed_table, conv_w,
                                                     conv_b, out_w, out_b);
    crf_kernel<<<dim3(BB, 3), 32>>>(tag_id, start_trans, end_trans, trans);
    final_kernel<<<1, 64>>>((float*)d_out);
}

// round 5
// speedup vs baseline: 2.6134x; 1.1632x over previous
#include <cuda_runtime.h>
#include <cuda_fp16.h>
#include <math.h>

#define BB 64
#define SS 4096
#define EE 50
#define TT 20

#define CS 128
#define HALO 5
#define RR (CS + 2*HALO)          // 138 positions
#define NP 9                      // positions per strip
#define NSTRIP 16                 // 16*9 = 144 >= 138
#define NQUAD 14                  // 14 quads = 28 pairs = 56 channels (50 real + 6 pad)
#define CPAD 56
#define NPAIR 28
#define XSTR2 146                 // half2 row stride (pos -1..144)
#define NTHREADS (NQUAD * NSTRIP) // 224

#define WS2_N (150 * NPAIR)       // 4200 half2
#define XS2_N (CPAD * XSTR2)      // 8176 half2
#define SMEM_BYTES ((WS2_N + XS2_N) * 4 + NPAIR * 8 + (1000 + 20) * 4)

__device__ float g_em[(size_t)SS * BB * TT];           // raw emissions [s][b][t]
__device__ float g_ee[(size_t)(SS + 40) * BB * TT];    // exp(emissions), padded for prefetch
__device__ float g_num[BB];
__device__ float g_fvec[BB][TT];
__device__ float g_bvec[BB][TT];
__device__ float g_fL[BB];
__device__ float g_bL[BB];

// ---------------------------------------------------------------------------
// Fused: embed gather -> 5x (conv1d + swish residual) -> emissions (+exp)
// grid (32, 64), 224 threads = (14 channel-quads) x (16 strips), smem ~53.8KB
// Register blocking: each thread owns 2 channel-PAIRS x 9 positions.
// Per i: 11 x LDS + 6 w LDS feed 54 HFMA2  (ratio 0.31 vs R4's 0.52).
// ---------------------------------------------------------------------------
__global__ __launch_bounds__(NTHREADS, 4)
void conv_emit_kernel(const int* __restrict__ token_id,
                      const float* __restrict__ embed_table,
                      const float* __restrict__ conv_w,
                      const float* __restrict__ conv_b,
                      const float* __restrict__ out_w,
                      const float* __restrict__ out_b)
{
    extern __shared__ __half2 smh2[];
    __half2* ws2 = smh2;                  // [(i*3+k)][pair]  row stride NPAIR
    __half2* xs2 = ws2 + WS2_N;           // [chan][idx] duplicated (h,h)
    float2*  cb2 = (float2*)(xs2 + XS2_N);// 28
    float*   ow  = (float*)(cb2 + NPAIR); // [t][e] 1000
    float*   ob  = ow + 1000;             // 20

    const int tid = threadIdx.x;
    const int b   = blockIdx.y;
    const int s0  = blockIdx.x * CS;

    // paired conv weights: ws2[row*28+pair] = (w[2p][row], w[2p+1][row]); pad pairs -> 0
    for (int idx = tid; idx < WS2_N; idx += NTHREADS) {
        int row = idx / NPAIR; int pair = idx - row * NPAIR;
        int c0 = 2 * pair, c1 = c0 + 1;
        float a = (c0 < EE) ? conv_w[c0 * 150 + row] : 0.0f;
        float c = (c1 < EE) ? conv_w[c1 * 150 + row] : 0.0f;
        ws2[idx] = __floats2half2_rn(a, c);
    }
    for (int idx = tid; idx < 1000; idx += NTHREADS) ow[idx] = out_w[idx];
    if (tid < NPAIR) {
        float a = (2*tid   < EE) ? conv_b[2*tid]   : 0.0f;
        float c = (2*tid+1 < EE) ? conv_b[2*tid+1] : 0.0f;
        cb2[tid] = make_float2(a, c);
    }
    if (tid < 20) ob[tid] = out_b[tid];

    // zero xs2 (covers pad channels + halo), then gather embeddings duplicated
    for (int idx = tid; idx < XS2_N; idx += NTHREADS) xs2[idx] = __floats2half2_rn(0.f, 0.f);
    __syncthreads();
    for (int idx = tid; idx < EE * RR; idx += NTHREADS) {
        int p = idx / EE; int e = idx - p * EE;
        int s = s0 - HALO + p;
        if (s >= 0 && s < SS) {
            int tok = token_id[b * SS + s];
            float v = embed_table[tok * EE + e];
            xs2[e * XSTR2 + p + 1] = __floats2half2_rn(v, v);
        }
    }
    __syncthreads();

    const int strip = tid & 15;
    const int g     = tid >> 4;            // 0..13
    const int pb    = strip * NP;
    const int pad_lo = (s0 == 0) ? HALO : 0;
    int pad_hi = SS - s0 + HALO; if (pad_hi > RR) pad_hi = RR;

    for (int iter = 1; iter <= 5; ++iter) {
        __half2 acc0[NP], acc1[NP];
        #pragma unroll
        for (int j = 0; j < NP; ++j) {
            acc0[j] = __floats2half2_rn(0.f, 0.f);
            acc1[j] = __floats2half2_rn(0.f, 0.f);
        }

        const __half2* wp = ws2 + 2 * g;       // pairs 2g, 2g+1
        const __half2* xp = xs2 + pb;          // xp[0] = position pb-1
        #pragma unroll 1
        for (int i = 0; i < EE; ++i) {
            __half2 w0a = wp[0],          w0b = wp[1];
            __half2 w1a = wp[NPAIR],      w1b = wp[NPAIR + 1];
            __half2 w2a = wp[2*NPAIR],    w2b = wp[2*NPAIR + 1];
            __half2 xv[NP + 2];
            #pragma unroll
            for (int j = 0; j < NP + 2; ++j) xv[j] = xp[j];
            #pragma unroll
            for (int j = 0; j < NP; ++j) {
                acc0[j] = __hfma2(w0a, xv[j],     acc0[j]);
                acc1[j] = __hfma2(w0b, xv[j],     acc1[j]);
                acc0[j] = __hfma2(w1a, xv[j + 1], acc0[j]);
                acc1[j] = __hfma2(w1b, xv[j + 1], acc1[j]);
                acc0[j] = __hfma2(w2a, xv[j + 2], acc0[j]);
                acc1[j] = __hfma2(w2b, xv[j + 2], acc1[j]);
            }
            wp += 3 * NPAIR;
            xp += XSTR2;
        }
        __syncthreads();

        int lo = (iter > pad_lo) ? iter : pad_lo;
        int hi = RR - iter; if (hi > pad_hi) hi = pad_hi;
        #pragma unroll
        for (int pr = 0; pr < 2; ++pr) {
            const float2 cb = cb2[2 * g + pr];
            const int o0 = 4 * g + 2 * pr, o1 = o0 + 1;
            #pragma unroll
            for (int j = 0; j < NP; ++j) {
                int p = pb + j;
                if (p >= lo && p < hi) {
                    __half2 a = pr ? acc1[j] : acc0[j];
                    float y0 = __low2float(a)  + cb.x;
                    float y1 = __high2float(a) + cb.y;
                    float sw0 = __fdividef(y0, 1.0f + __expf(-y0));
                    float sw1 = __fdividef(y1, 1.0f + __expf(-y1));
                    int i0 = o0 * XSTR2 + p + 1;
                    int i1 = o1 * XSTR2 + p + 1;
                    float nx0 = __low2float(xs2[i0]) + sw0;
                    float nx1 = __low2float(xs2[i1]) + sw1;
                    xs2[i0] = __floats2half2_rn(nx0, nx0);
                    xs2[i1] = __floats2half2_rn(nx1, nx1);
                }
            }
        }
        __syncthreads();
    }

    // emissions for q in [0, CS)
    for (int idx = tid; idx < TT * CS; idx += NTHREADS) {
        int t = idx % TT;
        int q = idx / TT;
        int p = q + HALO;
        int s = s0 + q;
        float acc = ob[t];
        const float* owt = &ow[t * EE];
        #pragma unroll 5
        for (int e = 0; e < EE; ++e)
            acc = fmaf(__low2float(xs2[e * XSTR2 + p + 1]), owt[e], acc);
        int gi = (s * BB + b) * TT + t;
        g_em[gi] = acc;
        g_ee[gi] = __expf(acc);
    }
}

// ===========================================================================
// CRF: grid (BB, 3) x 32 threads. Meet-in-the-middle + DEFERRED renorm:
// measure m = shfl(val,0) at group end, apply rcp(m) one group later —
// shfl/rcp/log2 run off the critical scan chain.
// ===========================================================================
__device__ __forceinline__ float crf_dot(float c, const float* E)
{
    float a0 = 0.f, a1 = 0.f, a2 = 0.f, a3 = 0.f;
    #pragma unroll
    for (int i = 0; i < TT; i += 4) {
        a0 = fmaf(__shfl_sync(0xffffffffu, c, i + 0), E[i + 0], a0);
        a1 = fmaf(__shfl_sync(0xffffffffu, c, i + 1), E[i + 1], a1);
        a2 = fmaf(__shfl_sync(0xffffffffu, c, i + 2), E[i + 2], a2);
        a3 = fmaf(__shfl_sync(0xffffffffu, c, i + 3), E[i + 3], a3);
    }
    return (a0 + a1) + (a2 + a3);
}

__global__ void crf_kernel(const int* __restrict__ tag,
                           const float* __restrict__ start_trans,
                           const float* __restrict__ end_trans,
                           const float* __restrict__ trans)
{
    const int b = blockIdx.x;
    const int dir = blockIdx.y;
    const int j = threadIdx.x;
    const bool ok = (j < TT);
    const int jj = ok ? j : 0;

    if (dir == 2) {
        float sum = 0.0f;
        for (int s = j; s < SS; s += 32) {
            int tg = tag[b * SS + s];
            sum += g_em[(s * BB + b) * TT + tg];
            if (s > 0)      sum += trans[tag[b * SS + s - 1] * TT + tg];
            if (s == 0)     sum += start_trans[tg];
            if (s == SS-1)  sum += end_trans[tg];
        }
        #pragma unroll
        for (int o = 16; o > 0; o >>= 1) sum += __shfl_xor_sync(0xffffffffu, sum, o);
        if (j == 0) g_num[b] = sum;
        return;
    }

    float E[TT];
    float val, L = 0.0f;
    float ea[8], eb[8];
    float rinv = 1.0f, lg = 0.0f, m;

    if (dir == 0) {
        // forward: lane j holds alpha[j]; E[i] = exp(trans[i][j]); t = 1..2048
        #pragma unroll
        for (int i = 0; i < TT; ++i) E[i] = ok ? __expf(trans[i * TT + jj]) : 0.0f;
        val = ok ? __expf(start_trans[jj]) * g_ee[(0 * BB + b) * TT + jj] : 0.0f;
        #pragma unroll
        for (int k = 0; k < 8; ++k) ea[k] = g_ee[((1 + k) * BB + b) * TT + jj];
        for (int g = 0; g < 256; g += 2) {
            int t1 = 1 + (g + 1) * 8;
            #pragma unroll
            for (int k = 0; k < 8; ++k) eb[k] = g_ee[((t1 + k) * BB + b) * TT + jj];
            #pragma unroll
            for (int k = 0; k < 8; ++k) val = ea[k] * crf_dot(val, E);
            val *= rinv; L += lg;
            m = __shfl_sync(0xffffffffu, val, 0);
            rinv = __frcp_rn(m); lg = __log2f(m);
            int t2 = 1 + (g + 2) * 8;
            #pragma unroll
            for (int k = 0; k < 8; ++k) ea[k] = g_ee[((t2 + k) * BB + b) * TT + jj];
            #pragma unroll
            for (int k = 0; k < 8; ++k) val = eb[k] * crf_dot(val, E);
            val *= rinv; L += lg;
            m = __shfl_sync(0xffffffffu, val, 0);
            rinv = __frcp_rn(m); lg = __log2f(m);
        }
        val *= rinv; L += lg;   // apply last pending scale
        if (ok) g_fvec[b][jj] = val;
        if (j == 0) g_fL[b] = L;
    } else {
        // backward: lane j holds beta[j]; E[i] = exp(trans[j][i]); 2047 steps
        #pragma unroll
        for (int i = 0; i < TT; ++i) E[i] = ok ? __expf(trans[jj * TT + i]) : 0.0f;
        val = ok ? __expf(end_trans[jj]) : 0.0f;
        #pragma unroll
        for (int k = 0; k < 8; ++k) ea[k] = g_ee[((4095 - k) * BB + b) * TT + jj];
        for (int g = 0; g < 256; g += 2) {
            int m1 = (g + 1) * 8;
            #pragma unroll
            for (int k = 0; k < 8; ++k) {
                int t = 4095 - (m1 + k);
                eb[k] = (t >= 0) ? g_ee[(t * BB + b) * TT + jj] : 0.0f;
            }
            int m0 = g * 8;
            #pragma unroll
            for (int k = 0; k < 8; ++k)
                if (m0 + k < 2047) val = crf_dot(ea[k] * val, E);
            val *= rinv; L += lg;
            m = __shfl_sync(0xffffffffu, val, 0);
            rinv = __frcp_rn(m); lg = __log2f(m);
            int m2 = (g + 2) * 8;
            #pragma unroll
            for (int k = 0; k < 8; ++k) {
                int t = 4095 - (m2 + k);
                ea[k] = (t >= 0) ? g_ee[(t * BB + b) * TT + jj] : 0.0f;
            }
            #pragma unroll
            for (int k = 0; k < 8; ++k)
                if (m1 + k < 2047) val = crf_dot(eb[k] * val, E);
            val *= rinv; L += lg;
            m = __shfl_sync(0xffffffffu, val, 0);
            rinv = __frcp_rn(m); lg = __log2f(m);
        }
        val *= rinv; L += lg;
        if (ok) g_bvec[b][jj] = val;
        if (j == 0) g_bL[b] = L;
    }
}

// ===========================================================================
// Combine: den_b = ln2*(Lf+Lb) + log(sum alpha*beta); out = sum(den - num)
// ===========================================================================
__global__ void final_kernel(float* __restrict__ out)
{
    __shared__ float red[64];
    int t = threadIdx.x;
    float s = 0.0f;
    #pragma unroll
    for (int i = 0; i < TT; ++i) s += g_fvec[t][i] * g_bvec[t][i];
    float den = (g_fL[t] + g_bL[t]) * 0.69314718055994531f + logf(s);
    red[t] = den - g_num[t];
    __syncthreads();
    for (int k = 32; k > 0; k >>= 1) {
        if (t < k) red[t] += red[t + k];
        __syncthreads();
    }
    if (t == 0) out[0] = red[0];
}

extern "C" void kernel_launch(void* const* d_in, const int* in_sizes, int n_in,
                              void* d_out, int out_size)
{
    const int*   token_id    = (const int*)d_in[0];
    const int*   tag_id      = (const int*)d_in[1];
    const float* embed_table = (const float*)d_in[2];
    const float* conv_w      = (const float*)d_in[3];
    const float* conv_b      = (const float*)d_in[4];
    const float* out_w       = (const float*)d_in[5];
    const float* out_b       = (const float*)d_in[6];
    const float* start_trans = (const float*)d_in[7];
    const float* end_trans   = (const float*)d_in[8];
    const float* trans       = (const float*)d_in[9];

    cudaFuncSetAttribute(conv_emit_kernel,
                         cudaFuncAttributeMaxDynamicSharedMemorySize, SMEM_BYTES);

    dim3 grid(SS / CS, BB);
    conv_emit_kernel<<<grid, NTHREADS, SMEM_BYTES>>>(token_id, embed_table, conv_w,
                                                     conv_b, out_w, out_b);
    crf_kernel<<<dim3(BB, 3), 32>>>(tag_id, start_trans, end_trans, trans);
    final_kernel<<<1, 64>>>((float*)d_out);
}

// round 6
// speedup vs baseline: 3.9231x; 1.5011x over previous
#include <cuda_runtime.h>
#include <cuda_fp16.h>
#include <stdint.h>
#include <math.h>

#define BB 64
#define SS 4096
#define EE 50
#define TT 20

#define CS 128
#define HALO 5
#define RR 138              // positions p = 0..137, s = s0 - 5 + p
#define XROWS 148           // storage row = p + 1, p in -1..146
#define XSTR 72             // halves per X row (144 B) -> conflict-free ldmatrix
#define ASTR 72             // halves per A row

// smem layout (bytes)
#define SM_A   0                        // 3 * 64 * 72 * 2 = 27648
#define SM_X   27648                    // 148 * 72 * 2    = 21312
#define SM_OW  (SM_X + XROWS*XSTR*2)    // 48960: out_w 1000 f32
#define SM_OB  (SM_OW + 4000)
#define SM_CB  (SM_OB + 80)             // conv bias padded to 64
#define SMEM_TOTAL (SM_CB + 256)

__device__ float g_em[(size_t)SS * BB * TT];
__device__ float g_ee[(size_t)(SS + 40) * BB * TT];
__device__ float g_num[BB];
__device__ float g_fvec[BB][TT];
__device__ float g_bvec[BB][TT];
__device__ float g_fL[BB];
__device__ float g_bL[BB];

__device__ __forceinline__ uint32_t smem_u32(const void* p) {
    uint32_t a;
    asm("{ .reg .u64 t; cvta.to.shared.u64 t, %1; cvt.u32.u64 %0, t; }" : "=r"(a) : "l"(p));
    return a;
}
__device__ __forceinline__ void ldsm_x4(uint32_t a, uint32_t r[4]) {
    asm volatile("ldmatrix.sync.aligned.m8n8.x4.shared.b16 {%0,%1,%2,%3}, [%4];"
                 : "=r"(r[0]), "=r"(r[1]), "=r"(r[2]), "=r"(r[3]) : "r"(a));
}
__device__ __forceinline__ void ldsm_x2(uint32_t a, uint32_t r[2]) {
    asm volatile("ldmatrix.sync.aligned.m8n8.x2.shared.b16 {%0,%1}, [%2];"
                 : "=r"(r[0]), "=r"(r[1]) : "r"(a));
}
__device__ __forceinline__ void mma16816(float d[4], const uint32_t a[4], const uint32_t b[2]) {
    asm volatile("mma.sync.aligned.m16n8k16.row.col.f32.f16.f16.f32 "
                 "{%0,%1,%2,%3}, {%4,%5,%6,%7}, {%8,%9}, {%0,%1,%2,%3};"
                 : "+f"(d[0]), "+f"(d[1]), "+f"(d[2]), "+f"(d[3])
                 : "r"(a[0]), "r"(a[1]), "r"(a[2]), "r"(a[3]), "r"(b[0]), "r"(b[1]));
}

// ===========================================================================
// Conv stack on mma.sync tensor cores.
// grid (32, 64), 256 threads = 8 warps: warp w -> m-tile (w&3), n-half (w>>2).
// X[p][i] half, row stride 72; B frag = ldmatrix.x2(rows p, cols i), tap kk
// is a +kk row offset. A frags resident in registers for all 5 layers.
// ===========================================================================
__global__ __launch_bounds__(256, 2)
void conv_emit_kernel(const int* __restrict__ token_id,
                      const float* __restrict__ embed_table,
                      const float* __restrict__ conv_w,
                      const float* __restrict__ conv_b,
                      const float* __restrict__ out_w,
                      const float* __restrict__ out_b)
{
    extern __shared__ char smem[];
    __half* Ah = (__half*)(smem + SM_A);
    __half* Xh = (__half*)(smem + SM_X);
    float*  ow = (float*)(smem + SM_OW);
    float*  ob = (float*)(smem + SM_OB);
    float*  cb = (float*)(smem + SM_CB);

    const int tid = threadIdx.x;
    const int b   = blockIdx.y;
    const int s0  = blockIdx.x * CS;

    // zero A + X regions
    for (int i = tid; i < SM_OW / 4; i += 256) ((uint32_t*)smem)[i] = 0u;
    __syncthreads();

    // A_kk[o][i] = conv_w[o][i][kk]
    for (int idx = tid; idx < 7500; idx += 256) {
        int o = idx / 150, rem = idx - o * 150;
        int i = rem / 3,   k = rem - i * 3;
        Ah[k * 64 * ASTR + o * ASTR + i] = __float2half(conv_w[idx]);
    }
    for (int i = tid; i < 1000; i += 256) ow[i] = out_w[i];
    if (tid < TT) ob[tid] = out_b[tid];
    if (tid < 64) cb[tid] = (tid < EE) ? conv_b[tid] : 0.0f;

    // embedding gather into X rows p+1 (valid s only; rest stays zero)
    for (int idx = tid; idx < RR * EE; idx += 256) {
        int p = idx / EE, e = idx - p * EE;
        int s = s0 - HALO + p;
        if (s >= 0 && s < SS) {
            int tok = token_id[b * SS + s];
            Xh[(p + 1) * XSTR + e] = __float2half(embed_table[tok * EE + e]);
        }
    }
    __syncthreads();

    const int lane = tid & 31, w = tid >> 5;
    const int m0 = (w & 3) * 16;
    const int n0base = (w >> 2) * 72;        // n-half: 9 n-tiles of 8

    const uint32_t su = smem_u32(smem);
    const uint32_t Au = su + SM_A, Xu = su + SM_X;

    // A fragments: 3 kk x 4 ksteps, resident for all layers
    uint32_t af[12][4];
    {
        const int arow  = m0 + (lane & 15);
        const int acolh = 8 * (lane >> 4);
        #pragma unroll
        for (int kk = 0; kk < 3; ++kk)
            #pragma unroll
            for (int ks = 0; ks < 4; ++ks)
                ldsm_x4(Au + kk * (64 * ASTR * 2) + arow * (ASTR * 2)
                           + (16 * ks + acolh) * 2, af[kk * 4 + ks]);
    }

    const int pad_lo = (s0 == 0) ? HALO : 0;
    int seq_hi = SS - s0 + HALO; if (seq_hi > RR) seq_hi = RR;
    const int gid = lane >> 2, tig = lane & 3;
    const int o0 = m0 + gid, o1 = o0 + 8;
    const float cb0 = cb[o0], cb1 = cb[o1];
    const int brow  = lane & 7;
    const int bcol8 = 8 * ((lane >> 3) & 1);

    #pragma unroll 1
    for (int l = 1; l <= 5; ++l) {
        float acc[9][4];
        #pragma unroll
        for (int nt = 0; nt < 9; ++nt)
            #pragma unroll
            for (int r = 0; r < 4; ++r) acc[nt][r] = 0.0f;

        #pragma unroll
        for (int kk = 0; kk < 3; ++kk)
            #pragma unroll
            for (int ks = 0; ks < 4; ++ks) {
                uint32_t base = Xu + (n0base + brow + kk) * (XSTR * 2)
                                   + (16 * ks + bcol8) * 2;
                #pragma unroll
                for (int nt = 0; nt < 9; ++nt) {
                    uint32_t bf[2];
                    ldsm_x2(base + nt * (8 * XSTR * 2), bf);
                    mma16816(acc[nt], af[kk * 4 + ks], bf);
                }
            }
        __syncthreads();   // all ldmatrix reads done before X is overwritten

        int lo = (l > pad_lo) ? l : pad_lo;
        int hi = RR - l; if (hi > seq_hi) hi = seq_hi;

        #pragma unroll
        for (int nt = 0; nt < 9; ++nt) {
            int p0 = n0base + nt * 8 + 2 * tig;
            #pragma unroll
            for (int e4 = 0; e4 < 4; ++e4) {
                int o  = (e4 < 2) ? o0 : o1;
                int p  = p0 + (e4 & 1);
                float cbi = (e4 < 2) ? cb0 : cb1;
                if (p >= lo && p < hi) {
                    int xi = (p + 1) * XSTR + o;
                    float y = acc[nt][e4] + cbi;
                    float sw = __fdividef(y, 1.0f + __expf(-y));
                    float nx = __half2float(Xh[xi]) + sw;
                    Xh[xi] = __float2half(nx);
                }
            }
        }
        __syncthreads();   // X updated before next layer's ldmatrix
    }

    // emissions
    for (int idx = tid; idx < TT * CS; idx += 256) {
        int t = idx % TT;
        int q = idx / TT;
        int s = s0 + q;
        const __half* xr = &Xh[(q + HALO + 1) * XSTR];
        float acc = ob[t];
        const float* owt = &ow[t * EE];
        #pragma unroll 5
        for (int e = 0; e < EE; ++e) acc = fmaf(__half2float(xr[e]), owt[e], acc);
        int gi = (s * BB + b) * TT + t;
        g_em[gi] = acc;
        g_ee[gi] = __expf(acc);
    }
}

// ===========================================================================
// CRF: grid (BB, 3) x 32 threads. Meet-in-the-middle + deferred renorm.
// ===========================================================================
__device__ __forceinline__ float crf_dot(float c, const float* E)
{
    float a0 = 0.f, a1 = 0.f, a2 = 0.f, a3 = 0.f;
    #pragma unroll
    for (int i = 0; i < TT; i += 4) {
        a0 = fmaf(__shfl_sync(0xffffffffu, c, i + 0), E[i + 0], a0);
        a1 = fmaf(__shfl_sync(0xffffffffu, c, i + 1), E[i + 1], a1);
        a2 = fmaf(__shfl_sync(0xffffffffu, c, i + 2), E[i + 2], a2);
        a3 = fmaf(__shfl_sync(0xffffffffu, c, i + 3), E[i + 3], a3);
    }
    return (a0 + a1) + (a2 + a3);
}

__global__ void crf_kernel(const int* __restrict__ tag,
                           const float* __restrict__ start_trans,
                           const float* __restrict__ end_trans,
                           const float* __restrict__ trans)
{
    const int b = blockIdx.x;
    const int dir = blockIdx.y;
    const int j = threadIdx.x;
    const bool ok = (j < TT);
    const int jj = ok ? j : 0;

    if (dir == 2) {
        float sum = 0.0f;
        for (int s = j; s < SS; s += 32) {
            int tg = tag[b * SS + s];
            sum += g_em[(s * BB + b) * TT + tg];
            if (s > 0)      sum += trans[tag[b * SS + s - 1] * TT + tg];
            if (s == 0)     sum += start_trans[tg];
            if (s == SS-1)  sum += end_trans[tg];
        }
        #pragma unroll
        for (int o = 16; o > 0; o >>= 1) sum += __shfl_xor_sync(0xffffffffu, sum, o);
        if (j == 0) g_num[b] = sum;
        return;
    }

    float E[TT];
    float val, L = 0.0f;
    float ea[8], eb[8];
    float rinv = 1.0f, lg = 0.0f, m;

    if (dir == 0) {
        #pragma unroll
        for (int i = 0; i < TT; ++i) E[i] = ok ? __expf(trans[i * TT + jj]) : 0.0f;
        val = ok ? __expf(start_trans[jj]) * g_ee[(0 * BB + b) * TT + jj] : 0.0f;
        #pragma unroll
        for (int k = 0; k < 8; ++k) ea[k] = g_ee[((1 + k) * BB + b) * TT + jj];
        for (int g = 0; g < 256; g += 2) {
            int t1 = 1 + (g + 1) * 8;
            #pragma unroll
            for (int k = 0; k < 8; ++k) eb[k] = g_ee[((t1 + k) * BB + b) * TT + jj];
            #pragma unroll
            for (int k = 0; k < 8; ++k) val = ea[k] * crf_dot(val, E);
            val *= rinv; L += lg;
            m = __shfl_sync(0xffffffffu, val, 0);
            rinv = __frcp_rn(m); lg = __log2f(m);
            int t2 = 1 + (g + 2) * 8;
            #pragma unroll
            for (int k = 0; k < 8; ++k) ea[k] = g_ee[((t2 + k) * BB + b) * TT + jj];
            #pragma unroll
            for (int k = 0; k < 8; ++k) val = eb[k] * crf_dot(val, E);
            val *= rinv; L += lg;
            m = __shfl_sync(0xffffffffu, val, 0);
            rinv = __frcp_rn(m); lg = __log2f(m);
        }
        val *= rinv; L += lg;
        if (ok) g_fvec[b][jj] = val;
        if (j == 0) g_fL[b] = L;
    } else {
        #pragma unroll
        for (int i = 0; i < TT; ++i) E[i] = ok ? __expf(trans[jj * TT + i]) : 0.0f;
        val = ok ? __expf(end_trans[jj]) : 0.0f;
        #pragma unroll
        for (int k = 0; k < 8; ++k) ea[k] = g_ee[((4095 - k) * BB + b) * TT + jj];
        for (int g = 0; g < 256; g += 2) {
            int m1 = (g + 1) * 8;
            #pragma unroll
            for (int k = 0; k < 8; ++k) {
                int t = 4095 - (m1 + k);
                eb[k] = (t >= 0) ? g_ee[(t * BB + b) * TT + jj] : 0.0f;
            }
            int m0 = g * 8;
            #pragma unroll
            for (int k = 0; k < 8; ++k)
                if (m0 + k < 2047) val = crf_dot(ea[k] * val, E);
            val *= rinv; L += lg;
            m = __shfl_sync(0xffffffffu, val, 0);
            rinv = __frcp_rn(m); lg = __log2f(m);
            int m2 = (g + 2) * 8;
            #pragma unroll
            for (int k = 0; k < 8; ++k) {
                int t = 4095 - (m2 + k);
                ea[k] = (t >= 0) ? g_ee[(t * BB + b) * TT + jj] : 0.0f;
            }
            #pragma unroll
            for (int k = 0; k < 8; ++k)
                if (m1 + k < 2047) val = crf_dot(eb[k] * val, E);
            val *= rinv; L += lg;
            m = __shfl_sync(0xffffffffu, val, 0);
            rinv = __frcp_rn(m); lg = __log2f(m);
        }
        val *= rinv; L += lg;
        if (ok) g_bvec[b][jj] = val;
        if (j == 0) g_bL[b] = L;
    }
}

__global__ void final_kernel(float* __restrict__ out)
{
    __shared__ float red[64];
    int t = threadIdx.x;
    float s = 0.0f;
    #pragma unroll
    for (int i = 0; i < TT; ++i) s += g_fvec[t][i] * g_bvec[t][i];
    float den = (g_fL[t] + g_bL[t]) * 0.69314718055994531f + logf(s);
    red[t] = den - g_num[t];
    __syncthreads();
    for (int k = 32; k > 0; k >>= 1) {
        if (t < k) red[t] += red[t + k];
        __syncthreads();
    }
    if (t == 0) out[0] = red[0];
}

extern "C" void kernel_launch(void* const* d_in, const int* in_sizes, int n_in,
                              void* d_out, int out_size)
{
    const int*   token_id    = (const int*)d_in[0];
    const int*   tag_id      = (const int*)d_in[1];
    const float* embed_table = (const float*)d_in[2];
    const float* conv_w      = (const float*)d_in[3];
    const float* conv_b      = (const float*)d_in[4];
    const float* out_w       = (const float*)d_in[5];
    const float* out_b       = (const float*)d_in[6];
    const float* start_trans = (const float*)d_in[7];
    const float* end_trans   = (const float*)d_in[8];
    const float* trans       = (const float*)d_in[9];

    cudaFuncSetAttribute(conv_emit_kernel,
                         cudaFuncAttributeMaxDynamicSharedMemorySize, SMEM_TOTAL);

    dim3 grid(SS / CS, BB);
    conv_emit_kernel<<<grid, 256, SMEM_TOTAL>>>(token_id, embed_table, conv_w,
                                                conv_b, out_w, out_b);
    crf_kernel<<<dim3(BB, 3), 32>>>(tag_id, start_trans, end_trans, trans);
    final_kernel<<<1, 64>>>((float*)d_out);
}